// round 1
// baseline (speedup 1.0000x reference)
#include <cuda_runtime.h>
#include <math.h>
#include <stdint.h>

// ---------------- problem constants ----------------
constexpr int NN   = 50000;
constexpr int EE   = 800000;
constexpr int DIM  = 128;
constexpr int EDIM = 64;
constexpr int NH   = 8;     // heads
constexpr int HC   = 16;    // channels per head
constexpr int HID  = 512;   // FFN hidden
constexpr int KEU  = 2*DIM + EDIM;  // 320

// ---------------- scratch (__device__ globals; no allocs allowed) ----------------
__device__ float g_xin  [(size_t)NN*DIM];
__device__ float g_h    [(size_t)NN*DIM];
__device__ float g_qkvs [(size_t)NN*4*DIM];   // cols: q[0:128) k[128:256) v[256:384) skip[384:512)
__device__ float g_eproj[(size_t)EE*DIM];
__device__ float g_alpha[(size_t)EE*NH];      // alpha, then overwritten by pe
__device__ float g_amax [(size_t)NN*NH];
__device__ float g_denom[(size_t)NN*NH];
__device__ float g_agg  [(size_t)NN*DIM];
__device__ float g_xattn[(size_t)NN*DIM];
__device__ float g_h2   [(size_t)NN*DIM];
__device__ float g_ffn1 [(size_t)NN*HID];
__device__ float g_xn   [(size_t)NN*DIM];
__device__ int   g_deg  [NN];

// ---------------- helpers ----------------
__device__ __forceinline__ float warp_sum(float v) {
#pragma unroll
    for (int o = 16; o > 0; o >>= 1) v += __shfl_xor_sync(0xffffffffu, v, o);
    return v;
}

__device__ __forceinline__ void atomicMaxF(float* addr, float v) {
    if (v >= 0.0f) atomicMax((int*)addr, __float_as_int(v));
    else           atomicMin((unsigned int*)addr, __float_as_uint(v));
}

// ---------------- init ----------------
__global__ void k_init() {
    int i  = blockIdx.x * blockDim.x + threadIdx.x;
    int st = gridDim.x * blockDim.x;
    for (int j = i; j < NN*DIM; j += st) g_agg[j] = 0.0f;
    for (int j = i; j < NN*NH;  j += st) { g_denom[j] = 0.0f; g_amax[j] = -INFINITY; }
    for (int j = i; j < NN;     j += st) g_deg[j] = 0;
}

__global__ void k_deg(const int* __restrict__ src) {
    int i = blockIdx.x * blockDim.x + threadIdx.x;
    if (i < EE) atomicAdd(&g_deg[src[i]], 1);
}

// ---------------- node prep: x_in = x + deg_emb[clip(deg)], h = LN(x_in) ----------------
__global__ void k_node_prep(const float* __restrict__ x, const float* __restrict__ demb,
                            const float* __restrict__ g, const float* __restrict__ b) {
    int row = blockIdx.x * 8 + (threadIdx.x >> 5);
    if (row >= NN) return;
    int lane = threadIdx.x & 31;
    int d = g_deg[row]; if (d > 255) d = 255;
    float4 xv = *(const float4*)(x + (size_t)row*DIM + lane*4);
    float4 dv = *(const float4*)(demb + (size_t)d*DIM + lane*4);
    float4 xi = make_float4(xv.x+dv.x, xv.y+dv.y, xv.z+dv.z, xv.w+dv.w);
    *(float4*)(g_xin + (size_t)row*DIM + lane*4) = xi;
    float m = warp_sum(xi.x+xi.y+xi.z+xi.w) * (1.0f/128.0f);
    float4 dd = make_float4(xi.x-m, xi.y-m, xi.z-m, xi.w-m);
    float var = warp_sum(dd.x*dd.x+dd.y*dd.y+dd.z*dd.z+dd.w*dd.w) * (1.0f/128.0f);
    float inv = rsqrtf(var + 1e-5f);
    float4 gv = *(const float4*)(g + lane*4);
    float4 bv = *(const float4*)(b + lane*4);
    float4 h  = make_float4(dd.x*inv*gv.x+bv.x, dd.y*inv*gv.y+bv.y,
                            dd.z*inv*gv.z+bv.z, dd.w*inv*gv.w+bv.w);
    *(float4*)(g_h + (size_t)row*DIM + lane*4) = h;
}

// ---------------- generic tiled GEMM: C[m, coff+n] = A@B + bias (+epilogue) ----------------
// MODE 0: plain (+bias if non-null). MODE 1: exact GELU. MODE 2: + res[m,n].
template<int MODE>
__global__ void k_gemm(const float* __restrict__ A, int lda,
                       const float* __restrict__ B, int ldb,
                       const float* __restrict__ bias,
                       float* __restrict__ Co, int ldc, int coff,
                       const float* __restrict__ res, int ldr,
                       int M, int Nw, int K) {
    __shared__ float Ash[16][65];
    __shared__ float Bsh[16][64];
    const int m0 = blockIdx.y * 64, n0 = blockIdx.x * 64;
    const int tid = threadIdx.x;
    const int tx = tid & 15, ty = tid >> 4;
    const int arow = tid >> 2, ac4 = (tid & 3) * 4;
    const int brow = tid >> 4, bcol = (tid & 15) * 4;
    float acc[4][4];
#pragma unroll
    for (int i = 0; i < 4; i++)
#pragma unroll
        for (int j = 0; j < 4; j++) acc[i][j] = 0.0f;

    for (int k0 = 0; k0 < K; k0 += 16) {
        float4 av;
        if (m0 + arow < M) av = *(const float4*)(A + (size_t)(m0+arow)*lda + (k0+ac4));
        else av = make_float4(0,0,0,0);
        Ash[ac4+0][arow] = av.x; Ash[ac4+1][arow] = av.y;
        Ash[ac4+2][arow] = av.z; Ash[ac4+3][arow] = av.w;
        *(float4*)&Bsh[brow][bcol] = *(const float4*)(B + (size_t)(k0+brow)*ldb + (n0+bcol));
        __syncthreads();
#pragma unroll
        for (int kk = 0; kk < 16; kk++) {
            float a[4], bb[4];
#pragma unroll
            for (int i = 0; i < 4; i++) a[i]  = Ash[kk][ty*4+i];
#pragma unroll
            for (int j = 0; j < 4; j++) bb[j] = Bsh[kk][tx*4+j];
#pragma unroll
            for (int i = 0; i < 4; i++)
#pragma unroll
                for (int j = 0; j < 4; j++) acc[i][j] += a[i] * bb[j];
        }
        __syncthreads();
    }
#pragma unroll
    for (int i = 0; i < 4; i++) {
        int m = m0 + ty*4 + i;
        if (m >= M) continue;
#pragma unroll
        for (int j = 0; j < 4; j++) {
            int n = n0 + tx*4 + j;
            float c = acc[i][j];
            if (bias) c += bias[n];
            if (MODE == 1) c = 0.5f * c * (1.0f + erff(c * 0.70710678118654752f));
            if (MODE == 2) c += res[(size_t)m*ldr + n];
            Co[(size_t)m*ldc + coff + n] = c;
        }
    }
}

// ---------------- attention: alpha, softmax, aggregate ----------------
__global__ void k_alpha(const int* __restrict__ src, const int* __restrict__ dst) {
    int idx = blockIdx.x * blockDim.x + threadIdx.x;   // EE*NH threads
    int e = idx >> 3, hh = idx & 7;
    int s = src[e], d = dst[e];
    const float4* qp = (const float4*)(g_qkvs + (size_t)d*512 + hh*16);
    const float4* kp = (const float4*)(g_qkvs + (size_t)s*512 + 128 + hh*16);
    const float4* ep = (const float4*)(g_eproj + (size_t)e*128 + hh*16);
    float sum = 0.0f;
#pragma unroll
    for (int i = 0; i < 4; i++) {
        float4 q = qp[i], k = kp[i], ev = ep[i];
        sum += q.x*(k.x+ev.x) + q.y*(k.y+ev.y) + q.z*(k.z+ev.z) + q.w*(k.w+ev.w);
    }
    float a = sum * 0.25f;   // / sqrt(16)
    g_alpha[idx] = a;
    atomicMaxF(&g_amax[(size_t)d*NH + hh], a);
}

__global__ void k_pe(const int* __restrict__ dst) {
    int idx = blockIdx.x * blockDim.x + threadIdx.x;   // EE*NH
    int e = idx >> 3, hh = idx & 7;
    int d = dst[e];
    float p = expf(g_alpha[idx] - g_amax[(size_t)d*NH + hh]);
    g_alpha[idx] = p;
    atomicAdd(&g_denom[(size_t)d*NH + hh], p);
}

__global__ void k_agg(const int* __restrict__ src, const int* __restrict__ dst) {
    int idx = blockIdx.x * blockDim.x + threadIdx.x;   // EE*DIM
    int e = idx >> 7, c = idx & 127;
    int s = src[e], d = dst[e];
    int hh = c >> 4;
    float attn = g_alpha[(size_t)e*NH + hh] / g_denom[(size_t)d*NH + hh];
    float msg = attn * (g_qkvs[(size_t)s*512 + 256 + c] + g_eproj[(size_t)e*128 + c]);
    atomicAdd(&g_agg[(size_t)d*128 + c], msg);
}

// ---------------- node post: x_attn = x_in + agg + skip; h2 = LN(x_attn) ----------------
__global__ void k_node_post(const float* __restrict__ g, const float* __restrict__ b) {
    int row = blockIdx.x * 8 + (threadIdx.x >> 5);
    if (row >= NN) return;
    int lane = threadIdx.x & 31;
    float4 xi = *(const float4*)(g_xin + (size_t)row*DIM + lane*4);
    float4 ag = *(const float4*)(g_agg + (size_t)row*DIM + lane*4);
    float4 sk = *(const float4*)(g_qkvs + (size_t)row*512 + 384 + lane*4);
    float4 xa = make_float4(xi.x+ag.x+sk.x, xi.y+ag.y+sk.y, xi.z+ag.z+sk.z, xi.w+ag.w+sk.w);
    *(float4*)(g_xattn + (size_t)row*DIM + lane*4) = xa;
    float m = warp_sum(xa.x+xa.y+xa.z+xa.w) * (1.0f/128.0f);
    float4 dd = make_float4(xa.x-m, xa.y-m, xa.z-m, xa.w-m);
    float var = warp_sum(dd.x*dd.x+dd.y*dd.y+dd.z*dd.z+dd.w*dd.w) * (1.0f/128.0f);
    float inv = rsqrtf(var + 1e-5f);
    float4 gv = *(const float4*)(g + lane*4);
    float4 bv = *(const float4*)(b + lane*4);
    float4 h = make_float4(dd.x*inv*gv.x+bv.x, dd.y*inv*gv.y+bv.y,
                           dd.z*inv*gv.z+bv.z, dd.w*inv*gv.w+bv.w);
    *(float4*)(g_h2 + (size_t)row*DIM + lane*4) = h;
}

// ---------------- xn = LN(x_new, eu_ng, eu_nb) ----------------
__global__ void k_xn(const float* __restrict__ xnew,
                     const float* __restrict__ g, const float* __restrict__ b) {
    int row = blockIdx.x * 8 + (threadIdx.x >> 5);
    if (row >= NN) return;
    int lane = threadIdx.x & 31;
    float4 xv = *(const float4*)(xnew + (size_t)row*DIM + lane*4);
    float m = warp_sum(xv.x+xv.y+xv.z+xv.w) * (1.0f/128.0f);
    float4 dd = make_float4(xv.x-m, xv.y-m, xv.z-m, xv.w-m);
    float var = warp_sum(dd.x*dd.x+dd.y*dd.y+dd.z*dd.z+dd.w*dd.w) * (1.0f/128.0f);
    float inv = rsqrtf(var + 1e-5f);
    float4 gv = *(const float4*)(g + lane*4);
    float4 bv = *(const float4*)(b + lane*4);
    float4 h = make_float4(dd.x*inv*gv.x+bv.x, dd.y*inv*gv.y+bv.y,
                           dd.z*inv*gv.z+bv.z, dd.w*inv*gv.w+bv.w);
    *(float4*)(g_xn + (size_t)row*DIM + lane*4) = h;
}

// ---------------- edge update: gather-GEMM [32e x 320] @ [320 x 128] + fused gate+LN ----------------
__global__ void k_edge(const int* __restrict__ src, const int* __restrict__ dst,
                       const float* __restrict__ ea,
                       const float* __restrict__ W, const float* __restrict__ bvec,
                       const float* __restrict__ eg, const float* __restrict__ ebias,
                       float* __restrict__ out) {
    __shared__ float Ash[16][33];
    __shared__ float Bsh[16][128];
    __shared__ float raw[32][128];
    __shared__ int sidx[32], didx[32];
    const int tid = threadIdx.x;
    const int e0 = blockIdx.x * 32;
    if (tid < 32) { sidx[tid] = src[e0+tid]; didx[tid] = dst[e0+tid]; }
    __syncthreads();
    const int ty = tid >> 5, tx = tid & 31;
    float acc[4][4];
#pragma unroll
    for (int i = 0; i < 4; i++)
#pragma unroll
        for (int j = 0; j < 4; j++) acc[i][j] = 0.0f;

    for (int k0 = 0; k0 < KEU; k0 += 16) {
        if (tid < 128) {
            int r = tid >> 2, c4 = (tid & 3) * 4;
            const float* base; int col;
            if (k0 < 128)      { base = g_xn + (size_t)sidx[r]*128; col = k0 + c4; }
            else if (k0 < 256) { base = g_xn + (size_t)didx[r]*128; col = k0 - 128 + c4; }
            else               { base = ea + (size_t)(e0+r)*64;     col = k0 - 256 + c4; }
            float4 av = *(const float4*)(base + col);
            Ash[c4+0][r] = av.x; Ash[c4+1][r] = av.y;
            Ash[c4+2][r] = av.z; Ash[c4+3][r] = av.w;
        }
#pragma unroll
        for (int t = 0; t < 2; t++) {
            int id = tid + t*256;
            int r = id >> 5, c = (id & 31) * 4;
            *(float4*)&Bsh[r][c] = *(const float4*)(W + (size_t)(k0+r)*128 + c);
        }
        __syncthreads();
#pragma unroll
        for (int kk = 0; kk < 16; kk++) {
            float a[4], bb[4];
#pragma unroll
            for (int i = 0; i < 4; i++) a[i]  = Ash[kk][ty*4+i];
#pragma unroll
            for (int j = 0; j < 4; j++) bb[j] = Bsh[kk][tx*4+j];
#pragma unroll
            for (int i = 0; i < 4; i++)
#pragma unroll
                for (int j = 0; j < 4; j++) acc[i][j] += a[i] * bb[j];
        }
        __syncthreads();
    }
    // bias + relu -> smem
#pragma unroll
    for (int i = 0; i < 4; i++)
#pragma unroll
        for (int j = 0; j < 4; j++) {
            int n = tx*4 + j;
            raw[ty*4+i][n] = fmaxf(acc[i][j] + bvec[n], 0.0f);
        }
    __syncthreads();
    // fused: t = edge_attr + sigmoid(gate)*delta; LN over 64 features
    int r = tid >> 3, jl = tid & 7;
    float t[8]; float s = 0.0f;
#pragma unroll
    for (int i = 0; i < 8; i++) {
        int c = jl*8 + i;
        float dlt = raw[r][c];
        float gt  = raw[r][64 + c];
        float tv  = ea[(size_t)(e0+r)*64 + c] + dlt / (1.0f + expf(-gt));
        t[i] = tv; s += tv;
    }
    s += __shfl_xor_sync(0xffffffffu, s, 4, 8);
    s += __shfl_xor_sync(0xffffffffu, s, 2, 8);
    s += __shfl_xor_sync(0xffffffffu, s, 1, 8);
    float m = s * (1.0f/64.0f);
    float vs = 0.0f;
#pragma unroll
    for (int i = 0; i < 8; i++) { float dd = t[i] - m; vs += dd*dd; }
    vs += __shfl_xor_sync(0xffffffffu, vs, 4, 8);
    vs += __shfl_xor_sync(0xffffffffu, vs, 2, 8);
    vs += __shfl_xor_sync(0xffffffffu, vs, 1, 8);
    float inv = rsqrtf(vs * (1.0f/64.0f) + 1e-5f);
#pragma unroll
    for (int i = 0; i < 8; i++) {
        int c = jl*8 + i;
        out[(size_t)(e0+r)*64 + c] = (t[i] - m) * inv * eg[c] + ebias[c];
    }
}

// ---------------- launcher ----------------
extern "C" void kernel_launch(void* const* d_in, const int* in_sizes, int n_in,
                              void* d_out, int out_size) {
    const float* x     = (const float*)d_in[0];
    const int*   ei    = (const int*)  d_in[1];
    const float* ea    = (const float*)d_in[2];
    const float* demb  = (const float*)d_in[3];
    const float* ng    = (const float*)d_in[4];
    const float* nbv   = (const float*)d_in[5];
    const float* Wq    = (const float*)d_in[6];
    const float* bq    = (const float*)d_in[7];
    const float* Wk    = (const float*)d_in[8];
    const float* bk    = (const float*)d_in[9];
    const float* Wv    = (const float*)d_in[10];
    const float* bv    = (const float*)d_in[11];
    const float* We    = (const float*)d_in[12];
    const float* Wskip = (const float*)d_in[13];
    const float* bskip = (const float*)d_in[14];
    const float* W1    = (const float*)d_in[15];
    const float* b1    = (const float*)d_in[16];
    const float* W2    = (const float*)d_in[17];
    const float* b2    = (const float*)d_in[18];
    const float* eung  = (const float*)d_in[19];
    const float* eunb  = (const float*)d_in[20];
    const float* euW   = (const float*)d_in[21];
    const float* eub   = (const float*)d_in[22];
    const float* eueg  = (const float*)d_in[23];
    const float* eueb  = (const float*)d_in[24];
    float* out = (float*)d_out;

    const int* src = ei;
    const int* dst = ei + EE;

    // device-symbol addresses for GEMM args (host cannot take &g_* directly)
    static float *p_h = nullptr, *p_qkvs = nullptr, *p_eproj = nullptr,
                 *p_h2 = nullptr, *p_ffn1 = nullptr, *p_xattn = nullptr;
    if (!p_h) {
        cudaGetSymbolAddress((void**)&p_h,     g_h);
        cudaGetSymbolAddress((void**)&p_qkvs,  g_qkvs);
        cudaGetSymbolAddress((void**)&p_eproj, g_eproj);
        cudaGetSymbolAddress((void**)&p_h2,    g_h2);
        cudaGetSymbolAddress((void**)&p_ffn1,  g_ffn1);
        cudaGetSymbolAddress((void**)&p_xattn, g_xattn);
    }

    k_init<<<2048, 256>>>();
    k_deg<<<(EE + 255)/256, 256>>>(src);
    k_node_prep<<<(NN + 7)/8, 256>>>(x, demb, ng, nbv);

    dim3 gq(2, (NN + 63)/64);
    k_gemm<0><<<gq, 256>>>(p_h, 128, Wq,    128, bq,    p_qkvs, 512, 0,   nullptr, 0, NN, 128, 128);
    k_gemm<0><<<gq, 256>>>(p_h, 128, Wk,    128, bk,    p_qkvs, 512, 128, nullptr, 0, NN, 128, 128);
    k_gemm<0><<<gq, 256>>>(p_h, 128, Wv,    128, bv,    p_qkvs, 512, 256, nullptr, 0, NN, 128, 128);
    k_gemm<0><<<gq, 256>>>(p_h, 128, Wskip, 128, bskip, p_qkvs, 512, 384, nullptr, 0, NN, 128, 128);

    dim3 ge(2, EE/64);
    k_gemm<0><<<ge, 256>>>(ea, 64, We, 128, nullptr, p_eproj, 128, 0, nullptr, 0, EE, 128, 64);

    k_alpha<<<(EE*NH)/256, 256>>>(src, dst);
    k_pe   <<<(EE*NH)/256, 256>>>(dst);
    k_agg  <<<(EE*DIM)/256, 256>>>(src, dst);

    k_node_post<<<(NN + 7)/8, 256>>>(ng, nbv);

    dim3 gf1(8, (NN + 63)/64);
    k_gemm<1><<<gf1, 256>>>(p_h2, 128, W1, 512, b1, p_ffn1, 512, 0, nullptr, 0, NN, 512, 128);
    dim3 gf2(2, (NN + 63)/64);
    k_gemm<2><<<gf2, 256>>>(p_ffn1, 512, W2, 128, b2, out, 128, 0, p_xattn, 128, NN, 128, 512);

    k_xn<<<(NN + 7)/8, 256>>>(out, eung, eunb);
    k_edge<<<EE/32, 256>>>(src, dst, ea, euW, eub, eueg, eueb, out + (size_t)NN*DIM);
}

// round 3
// speedup vs baseline: 1.9355x; 1.9355x over previous
#include <cuda_runtime.h>
#include <math.h>
#include <stdint.h>

// ---------------- problem constants ----------------
constexpr int NN   = 50000;
constexpr int EE   = 800000;
constexpr int DIM  = 128;
constexpr int NH   = 8;
constexpr int HID  = 512;
constexpr int KEU  = 320;

// ---------------- scratch ----------------
__device__ float g_xin  [(size_t)NN*DIM];
__device__ float g_h    [(size_t)NN*DIM];
__device__ float g_qkvs [(size_t)NN*4*DIM];   // q[0:128) k[128:256) v[256:384) skip[384:512)
__device__ float g_eproj[(size_t)EE*DIM];
__device__ float g_alpha[(size_t)EE*NH];
__device__ float g_amax [(size_t)NN*NH];
__device__ float g_denom[(size_t)NN*NH];
__device__ float g_agg  [(size_t)NN*DIM];
__device__ float g_xattn[(size_t)NN*DIM];
__device__ float g_h2   [(size_t)NN*DIM];
__device__ float g_ffn1 [(size_t)NN*HID];
__device__ float g_xn   [(size_t)NN*DIM];
__device__ float g_W4   [(size_t)DIM*512];
__device__ float g_b4   [512];
__device__ int   g_deg  [NN];

// ---------------- helpers ----------------
__device__ __forceinline__ float warp_sum(float v) {
#pragma unroll
    for (int o = 16; o > 0; o >>= 1) v += __shfl_xor_sync(0xffffffffu, v, o);
    return v;
}
__device__ __forceinline__ void atomicMaxF(float* addr, float v) {
    if (v >= 0.0f) atomicMax((int*)addr, __float_as_int(v));
    else           atomicMin((unsigned int*)addr, __float_as_uint(v));
}

// ---------------- init / degree ----------------
__global__ void k_init() {
    int i  = blockIdx.x * blockDim.x + threadIdx.x;
    int st = gridDim.x * blockDim.x;
    for (int j = i; j < NN*DIM; j += st) g_agg[j] = 0.0f;
    for (int j = i; j < NN*NH;  j += st) { g_denom[j] = 0.0f; g_amax[j] = -INFINITY; }
    for (int j = i; j < NN;     j += st) g_deg[j] = 0;
}
__global__ void k_deg(const int* __restrict__ src) {
    int i = blockIdx.x * blockDim.x + threadIdx.x;
    if (i < EE) atomicAdd(&g_deg[src[i]], 1);
}
__global__ void k_pack(const float* __restrict__ Wq, const float* __restrict__ Wk,
                       const float* __restrict__ Wv, const float* __restrict__ Ws,
                       const float* __restrict__ bq, const float* __restrict__ bk,
                       const float* __restrict__ bv, const float* __restrict__ bs) {
    int i = blockIdx.x * blockDim.x + threadIdx.x;
    if (i < DIM*DIM) {
        int r = i >> 7, c = i & 127;
        g_W4[(size_t)r*512 +       c] = Wq[i];
        g_W4[(size_t)r*512 + 128 + c] = Wk[i];
        g_W4[(size_t)r*512 + 256 + c] = Wv[i];
        g_W4[(size_t)r*512 + 384 + c] = Ws[i];
    }
    if (i < 128) {
        g_b4[i] = bq[i]; g_b4[128+i] = bk[i]; g_b4[256+i] = bv[i]; g_b4[384+i] = bs[i];
    }
}

// ---------------- fused LN kernels ----------------
__global__ void k_node_prep(const float* __restrict__ x, const float* __restrict__ demb,
                            const float* __restrict__ g, const float* __restrict__ b) {
    int row = blockIdx.x * 8 + (threadIdx.x >> 5);
    if (row >= NN) return;
    int lane = threadIdx.x & 31;
    int d = g_deg[row]; if (d > 255) d = 255;
    float4 xv = *(const float4*)(x + (size_t)row*DIM + lane*4);
    float4 dv = *(const float4*)(demb + (size_t)d*DIM + lane*4);
    float4 xi = make_float4(xv.x+dv.x, xv.y+dv.y, xv.z+dv.z, xv.w+dv.w);
    *(float4*)(g_xin + (size_t)row*DIM + lane*4) = xi;
    float m = warp_sum(xi.x+xi.y+xi.z+xi.w) * (1.0f/128.0f);
    float4 dd = make_float4(xi.x-m, xi.y-m, xi.z-m, xi.w-m);
    float var = warp_sum(dd.x*dd.x+dd.y*dd.y+dd.z*dd.z+dd.w*dd.w) * (1.0f/128.0f);
    float inv = rsqrtf(var + 1e-5f);
    float4 gv = *(const float4*)(g + lane*4);
    float4 bv = *(const float4*)(b + lane*4);
    *(float4*)(g_h + (size_t)row*DIM + lane*4) =
        make_float4(dd.x*inv*gv.x+bv.x, dd.y*inv*gv.y+bv.y, dd.z*inv*gv.z+bv.z, dd.w*inv*gv.w+bv.w);
}

__global__ void k_node_post(const float* __restrict__ g, const float* __restrict__ b) {
    int row = blockIdx.x * 8 + (threadIdx.x >> 5);
    if (row >= NN) return;
    int lane = threadIdx.x & 31;
    float4 xi = *(const float4*)(g_xin + (size_t)row*DIM + lane*4);
    float4 ag = *(const float4*)(g_agg + (size_t)row*DIM + lane*4);
    float4 sk = *(const float4*)(g_qkvs + (size_t)row*512 + 384 + lane*4);
    float4 xa = make_float4(xi.x+ag.x+sk.x, xi.y+ag.y+sk.y, xi.z+ag.z+sk.z, xi.w+ag.w+sk.w);
    *(float4*)(g_xattn + (size_t)row*DIM + lane*4) = xa;
    float m = warp_sum(xa.x+xa.y+xa.z+xa.w) * (1.0f/128.0f);
    float4 dd = make_float4(xa.x-m, xa.y-m, xa.z-m, xa.w-m);
    float var = warp_sum(dd.x*dd.x+dd.y*dd.y+dd.z*dd.z+dd.w*dd.w) * (1.0f/128.0f);
    float inv = rsqrtf(var + 1e-5f);
    float4 gv = *(const float4*)(g + lane*4);
    float4 bv = *(const float4*)(b + lane*4);
    *(float4*)(g_h2 + (size_t)row*DIM + lane*4) =
        make_float4(dd.x*inv*gv.x+bv.x, dd.y*inv*gv.y+bv.y, dd.z*inv*gv.z+bv.z, dd.w*inv*gv.w+bv.w);
}

__global__ void k_xn(const float* __restrict__ xnew,
                     const float* __restrict__ g, const float* __restrict__ b) {
    int row = blockIdx.x * 8 + (threadIdx.x >> 5);
    if (row >= NN) return;
    int lane = threadIdx.x & 31;
    float4 xv = *(const float4*)(xnew + (size_t)row*DIM + lane*4);
    float m = warp_sum(xv.x+xv.y+xv.z+xv.w) * (1.0f/128.0f);
    float4 dd = make_float4(xv.x-m, xv.y-m, xv.z-m, xv.w-m);
    float var = warp_sum(dd.x*dd.x+dd.y*dd.y+dd.z*dd.z+dd.w*dd.w) * (1.0f/128.0f);
    float inv = rsqrtf(var + 1e-5f);
    float4 gv = *(const float4*)(g + lane*4);
    float4 bv = *(const float4*)(b + lane*4);
    *(float4*)(g_xn + (size_t)row*DIM + lane*4) =
        make_float4(dd.x*inv*gv.x+bv.x, dd.y*inv*gv.y+bv.y, dd.z*inv*gv.z+bv.z, dd.w*inv*gv.w+bv.w);
}

// ---------------- 128x128-tile GEMM, 8x8 micro-tile ----------------
// MODE 0: +bias. MODE 1: +bias, exact GELU. MODE 2: +bias +res.
template<int MODE>
__global__ void __launch_bounds__(256, 2)
k_gemm128(const float* __restrict__ A, int lda,
          const float* __restrict__ B, int ldb,
          const float* __restrict__ bias,
          float* __restrict__ Co, int ldc,
          const float* __restrict__ res, int ldr,
          int M, int K) {
    __shared__ float Ash[16][132];
    __shared__ float Bsh[16][132];
    const int m0 = blockIdx.y * 128, n0 = blockIdx.x * 128;
    const int tid = threadIdx.x;
    const int tx = tid & 15, ty = tid >> 4;
    const int lr = tid >> 1, lh = (tid & 1) * 8;     // A loader
    const int br = tid >> 4, bc = (tid & 15) * 8;    // B loader
    float acc[8][8] = {};

    for (int k0 = 0; k0 < K; k0 += 16) {
        float4 a0, a1;
        if (m0 + lr < M) {
            const float* ap = A + (size_t)(m0 + lr)*lda + k0 + lh;
            a0 = *(const float4*)ap; a1 = *(const float4*)(ap + 4);
        } else { a0 = make_float4(0,0,0,0); a1 = a0; }
        Ash[lh+0][lr] = a0.x; Ash[lh+1][lr] = a0.y; Ash[lh+2][lr] = a0.z; Ash[lh+3][lr] = a0.w;
        Ash[lh+4][lr] = a1.x; Ash[lh+5][lr] = a1.y; Ash[lh+6][lr] = a1.z; Ash[lh+7][lr] = a1.w;
        const float* bp = B + (size_t)(k0 + br)*ldb + n0 + bc;
        *(float4*)&Bsh[br][bc]   = *(const float4*)bp;
        *(float4*)&Bsh[br][bc+4] = *(const float4*)(bp + 4);
        __syncthreads();
#pragma unroll
        for (int kk = 0; kk < 16; kk++) {
            float a[8], b[8];
            *(float4*)&a[0] = *(const float4*)&Ash[kk][ty*8];
            *(float4*)&a[4] = *(const float4*)&Ash[kk][ty*8+4];
            *(float4*)&b[0] = *(const float4*)&Bsh[kk][tx*8];
            *(float4*)&b[4] = *(const float4*)&Bsh[kk][tx*8+4];
#pragma unroll
            for (int i = 0; i < 8; i++)
#pragma unroll
                for (int j = 0; j < 8; j++) acc[i][j] += a[i] * b[j];
        }
        __syncthreads();
    }
#pragma unroll
    for (int i = 0; i < 8; i++) {
        int m = m0 + ty*8 + i;
        if (m >= M) continue;
#pragma unroll
        for (int j4 = 0; j4 < 8; j4 += 4) {
            int n = n0 + tx*8 + j4;
            float4 bb = *(const float4*)(bias + n);
            float4 c = make_float4(acc[i][j4]+bb.x, acc[i][j4+1]+bb.y,
                                   acc[i][j4+2]+bb.z, acc[i][j4+3]+bb.w);
            if (MODE == 1) {
                c.x = 0.5f*c.x*(1.0f+erff(c.x*0.70710678118654752f));
                c.y = 0.5f*c.y*(1.0f+erff(c.y*0.70710678118654752f));
                c.z = 0.5f*c.z*(1.0f+erff(c.z*0.70710678118654752f));
                c.w = 0.5f*c.w*(1.0f+erff(c.w*0.70710678118654752f));
            }
            if (MODE == 2) {
                float4 rr = *(const float4*)(res + (size_t)m*ldr + n);
                c.x += rr.x; c.y += rr.y; c.z += rr.z; c.w += rr.w;
            }
            *(float4*)(Co + (size_t)m*ldc + n) = c;
        }
    }
}

// no-bias variant for eproj
__global__ void __launch_bounds__(256, 2)
k_gemm128_nb(const float* __restrict__ A, int lda,
             const float* __restrict__ B, int ldb,
             float* __restrict__ Co, int ldc, int M, int K) {
    __shared__ float Ash[16][132];
    __shared__ float Bsh[16][132];
    const int m0 = blockIdx.y * 128, n0 = blockIdx.x * 128;
    const int tid = threadIdx.x;
    const int tx = tid & 15, ty = tid >> 4;
    const int lr = tid >> 1, lh = (tid & 1) * 8;
    const int br = tid >> 4, bc = (tid & 15) * 8;
    float acc[8][8] = {};
    for (int k0 = 0; k0 < K; k0 += 16) {
        const float* ap = A + (size_t)(m0 + lr)*lda + k0 + lh;
        float4 a0 = *(const float4*)ap, a1 = *(const float4*)(ap + 4);
        Ash[lh+0][lr] = a0.x; Ash[lh+1][lr] = a0.y; Ash[lh+2][lr] = a0.z; Ash[lh+3][lr] = a0.w;
        Ash[lh+4][lr] = a1.x; Ash[lh+5][lr] = a1.y; Ash[lh+6][lr] = a1.z; Ash[lh+7][lr] = a1.w;
        const float* bp = B + (size_t)(k0 + br)*ldb + n0 + bc;
        *(float4*)&Bsh[br][bc]   = *(const float4*)bp;
        *(float4*)&Bsh[br][bc+4] = *(const float4*)(bp + 4);
        __syncthreads();
#pragma unroll
        for (int kk = 0; kk < 16; kk++) {
            float a[8], b[8];
            *(float4*)&a[0] = *(const float4*)&Ash[kk][ty*8];
            *(float4*)&a[4] = *(const float4*)&Ash[kk][ty*8+4];
            *(float4*)&b[0] = *(const float4*)&Bsh[kk][tx*8];
            *(float4*)&b[4] = *(const float4*)&Bsh[kk][tx*8+4];
#pragma unroll
            for (int i = 0; i < 8; i++)
#pragma unroll
                for (int j = 0; j < 8; j++) acc[i][j] += a[i] * b[j];
        }
        __syncthreads();
    }
#pragma unroll
    for (int i = 0; i < 8; i++) {
        int m = m0 + ty*8 + i;
#pragma unroll
        for (int j4 = 0; j4 < 8; j4 += 4) {
            int n = n0 + tx*8 + j4;
            *(float4*)(Co + (size_t)m*ldc + n) =
                make_float4(acc[i][j4], acc[i][j4+1], acc[i][j4+2], acc[i][j4+3]);
        }
    }
}

// ---------------- attention ----------------
__global__ void k_alpha(const int* __restrict__ src, const int* __restrict__ dst) {
    int idx = blockIdx.x * blockDim.x + threadIdx.x;   // EE*NH
    int e = idx >> 3, hh = idx & 7;
    int s = src[e], d = dst[e];
    const float4* qp = (const float4*)(g_qkvs + (size_t)d*512 + hh*16);
    const float4* kp = (const float4*)(g_qkvs + (size_t)s*512 + 128 + hh*16);
    const float4* ep = (const float4*)(g_eproj + (size_t)e*128 + hh*16);
    float sum = 0.0f;
#pragma unroll
    for (int i = 0; i < 4; i++) {
        float4 q = qp[i], k = kp[i], ev = ep[i];
        sum += q.x*(k.x+ev.x) + q.y*(k.y+ev.y) + q.z*(k.z+ev.z) + q.w*(k.w+ev.w);
    }
    float a = sum * 0.25f;
    g_alpha[idx] = a;
    atomicMaxF(&g_amax[(size_t)d*NH + hh], a);
}

__global__ void k_pe(const int* __restrict__ dst) {
    int idx = blockIdx.x * blockDim.x + threadIdx.x;   // EE*NH
    int e = idx >> 3, hh = idx & 7;
    int d = dst[e];
    float p = expf(g_alpha[idx] - g_amax[(size_t)d*NH + hh]);
    g_alpha[idx] = p;
    atomicAdd(&g_denom[(size_t)d*NH + hh], p);
}

__global__ void k_agg(const int* __restrict__ src, const int* __restrict__ dst) {
    int idx = blockIdx.x * blockDim.x + threadIdx.x;   // EE*32
    int e = idx >> 5, t = idx & 31;
    int s = src[e], d = dst[e];
    int hh = t >> 2;
    float attn = g_alpha[(size_t)e*NH + hh] / g_denom[(size_t)d*NH + hh];
    float4 v = *(const float4*)(g_qkvs + (size_t)s*512 + 256 + t*4);
    float4 ev = *(const float4*)(g_eproj + (size_t)e*128 + t*4);
    float* o = g_agg + (size_t)d*128 + t*4;
    atomicAdd(o+0, attn*(v.x+ev.x));
    atomicAdd(o+1, attn*(v.y+ev.y));
    atomicAdd(o+2, attn*(v.z+ev.z));
    atomicAdd(o+3, attn*(v.w+ev.w));
}

// ---------------- edge update: gather-GEMM 128e x 320 @ 320 x 128, fused gate+LN ----------------
__global__ void __launch_bounds__(256, 2)
k_edge128(const int* __restrict__ src, const int* __restrict__ dst,
          const float* __restrict__ ea,
          const float* __restrict__ W, const float* __restrict__ bvec,
          const float* __restrict__ eg, const float* __restrict__ ebias,
          float* __restrict__ out) {
    extern __shared__ float sm[];
    float (*Ash)[132] = (float(*)[132])sm;                 // 16 x 132
    float (*Bsh)[132] = (float(*)[132])(sm + 16*132);      // 16 x 132
    float (*raw)[132] = (float(*)[132])sm;                 // 128 x 132 (overlays Ash/Bsh after loop)
    __shared__ int sidx[128], didx[128];

    const int tid = threadIdx.x;
    const int e0 = blockIdx.x * 128;
    if (tid < 128) { sidx[tid] = src[e0+tid]; didx[tid] = dst[e0+tid]; }
    __syncthreads();

    const int tx = tid & 15, ty = tid >> 4;
    const int lr = tid >> 1, lh = (tid & 1) * 8;
    const int br = tid >> 4, bc = (tid & 15) * 8;
    float acc[8][8] = {};

    for (int k0 = 0; k0 < KEU; k0 += 16) {
        const float* base; int col;
        if (k0 < 128)      { base = g_xn + (size_t)sidx[lr]*128; col = k0 + lh; }
        else if (k0 < 256) { base = g_xn + (size_t)didx[lr]*128; col = k0 - 128 + lh; }
        else               { base = ea + (size_t)(e0+lr)*64;     col = k0 - 256 + lh; }
        float4 a0 = *(const float4*)(base + col);
        float4 a1 = *(const float4*)(base + col + 4);
        Ash[lh+0][lr] = a0.x; Ash[lh+1][lr] = a0.y; Ash[lh+2][lr] = a0.z; Ash[lh+3][lr] = a0.w;
        Ash[lh+4][lr] = a1.x; Ash[lh+5][lr] = a1.y; Ash[lh+6][lr] = a1.z; Ash[lh+7][lr] = a1.w;
        const float* bp = W + (size_t)(k0 + br)*128 + bc;
        *(float4*)&Bsh[br][bc]   = *(const float4*)bp;
        *(float4*)&Bsh[br][bc+4] = *(const float4*)(bp + 4);
        __syncthreads();
#pragma unroll
        for (int kk = 0; kk < 16; kk++) {
            float a[8], b[8];
            *(float4*)&a[0] = *(const float4*)&Ash[kk][ty*8];
            *(float4*)&a[4] = *(const float4*)&Ash[kk][ty*8+4];
            *(float4*)&b[0] = *(const float4*)&Bsh[kk][tx*8];
            *(float4*)&b[4] = *(const float4*)&Bsh[kk][tx*8+4];
#pragma unroll
            for (int i = 0; i < 8; i++)
#pragma unroll
                for (int j = 0; j < 8; j++) acc[i][j] += a[i] * b[j];
        }
        __syncthreads();
    }

    // bias + relu -> raw smem (overlays dead A/B tiles)
#pragma unroll
    for (int i = 0; i < 8; i++) {
#pragma unroll
        for (int j4 = 0; j4 < 8; j4 += 4) {
            int n = tx*8 + j4;
            float4 bb = *(const float4*)(bvec + n);
            *(float4*)&raw[ty*8+i][n] =
                make_float4(fmaxf(acc[i][0+j4]+bb.x, 0.0f), fmaxf(acc[i][1+j4]+bb.y, 0.0f),
                            fmaxf(acc[i][2+j4]+bb.z, 0.0f), fmaxf(acc[i][3+j4]+bb.w, 0.0f));
        }
    }
    __syncthreads();

    // t = edge_attr + sigmoid(gate)*delta; LN over 64.
    // 4 threads/row, 16 cols each; two passes cover all 128 rows (256 threads).
#pragma unroll
    for (int half = 0; half < 2; half++) {
        int r = (tid >> 2) + half * 64;
        int q = tid & 3;
        float t[16]; float s = 0.0f;
#pragma unroll
        for (int i4 = 0; i4 < 16; i4 += 4) {
            int c = q*16 + i4;
            float4 e4 = *(const float4*)(ea + (size_t)(e0+r)*64 + c);
            t[i4+0] = e4.x + raw[r][c+0] / (1.0f + expf(-raw[r][64+c+0]));
            t[i4+1] = e4.y + raw[r][c+1] / (1.0f + expf(-raw[r][64+c+1]));
            t[i4+2] = e4.z + raw[r][c+2] / (1.0f + expf(-raw[r][64+c+2]));
            t[i4+3] = e4.w + raw[r][c+3] / (1.0f + expf(-raw[r][64+c+3]));
            s += t[i4+0] + t[i4+1] + t[i4+2] + t[i4+3];
        }
        s += __shfl_xor_sync(0xffffffffu, s, 1);
        s += __shfl_xor_sync(0xffffffffu, s, 2);
        float m = s * (1.0f/64.0f);
        float vs = 0.0f;
#pragma unroll
        for (int i = 0; i < 16; i++) { float dd = t[i] - m; vs += dd*dd; }
        vs += __shfl_xor_sync(0xffffffffu, vs, 1);
        vs += __shfl_xor_sync(0xffffffffu, vs, 2);
        float inv = rsqrtf(vs * (1.0f/64.0f) + 1e-5f);
#pragma unroll
        for (int i4 = 0; i4 < 16; i4 += 4) {
            int c = q*16 + i4;
            float4 gv = *(const float4*)(eg + c);
            float4 bb = *(const float4*)(ebias + c);
            *(float4*)(out + (size_t)(e0+r)*64 + c) =
                make_float4((t[i4+0]-m)*inv*gv.x+bb.x, (t[i4+1]-m)*inv*gv.y+bb.y,
                            (t[i4+2]-m)*inv*gv.z+bb.z, (t[i4+3]-m)*inv*gv.w+bb.w);
        }
    }
}

// ---------------- launcher ----------------
extern "C" void kernel_launch(void* const* d_in, const int* in_sizes, int n_in,
                              void* d_out, int out_size) {
    const float* x     = (const float*)d_in[0];
    const int*   ei    = (const int*)  d_in[1];
    const float* ea    = (const float*)d_in[2];
    const float* demb  = (const float*)d_in[3];
    const float* ng    = (const float*)d_in[4];
    const float* nbv   = (const float*)d_in[5];
    const float* Wq    = (const float*)d_in[6];
    const float* bq    = (const float*)d_in[7];
    const float* Wk    = (const float*)d_in[8];
    const float* bk    = (const float*)d_in[9];
    const float* Wv    = (const float*)d_in[10];
    const float* bv    = (const float*)d_in[11];
    const float* We    = (const float*)d_in[12];
    const float* Wskip = (const float*)d_in[13];
    const float* bskip = (const float*)d_in[14];
    const float* W1    = (const float*)d_in[15];
    const float* b1    = (const float*)d_in[16];
    const float* W2    = (const float*)d_in[17];
    const float* b2    = (const float*)d_in[18];
    const float* eung  = (const float*)d_in[19];
    const float* eunb  = (const float*)d_in[20];
    const float* euW   = (const float*)d_in[21];
    const float* eub   = (const float*)d_in[22];
    const float* eueg  = (const float*)d_in[23];
    const float* eueb  = (const float*)d_in[24];
    float* out = (float*)d_out;

    const int* src = ei;
    const int* dst = ei + EE;

    static float *p_h = nullptr, *p_qkvs = nullptr, *p_eproj = nullptr,
                 *p_h2 = nullptr, *p_ffn1 = nullptr, *p_xattn = nullptr,
                 *p_W4 = nullptr, *p_b4 = nullptr;
    static bool inited = false;
    if (!inited) {
        cudaGetSymbolAddress((void**)&p_h,     g_h);
        cudaGetSymbolAddress((void**)&p_qkvs,  g_qkvs);
        cudaGetSymbolAddress((void**)&p_eproj, g_eproj);
        cudaGetSymbolAddress((void**)&p_h2,    g_h2);
        cudaGetSymbolAddress((void**)&p_ffn1,  g_ffn1);
        cudaGetSymbolAddress((void**)&p_xattn, g_xattn);
        cudaGetSymbolAddress((void**)&p_W4,    g_W4);
        cudaGetSymbolAddress((void**)&p_b4,    g_b4);
        cudaFuncSetAttribute(k_edge128, cudaFuncAttributeMaxDynamicSharedMemorySize, 128*132*4);
        inited = true;
    }

    k_init<<<2048, 256>>>();
    k_deg<<<(EE + 255)/256, 256>>>(src);
    k_pack<<<64, 256>>>(Wq, Wk, Wv, Wskip, bq, bk, bv, bskip);
    k_node_prep<<<(NN + 7)/8, 256>>>(x, demb, ng, nbv);

    // fused QKV+skip: [50000x128] @ [128x512]
    k_gemm128<0><<<dim3(4, (NN+127)/128), 256>>>(p_h, 128, p_W4, 512, p_b4, p_qkvs, 512,
                                                 nullptr, 0, NN, 128);
    // edge proj: [800000x64] @ [64x128]
    k_gemm128_nb<<<dim3(1, EE/128), 256>>>(ea, 64, We, 128, p_eproj, 128, EE, 64);

    k_alpha<<<(EE*NH)/256, 256>>>(src, dst);
    k_pe   <<<(EE*NH)/256, 256>>>(dst);
    k_agg  <<<(EE*32)/256, 256>>>(src, dst);

    k_node_post<<<(NN + 7)/8, 256>>>(ng, nbv);

    // FFN
    k_gemm128<1><<<dim3(4, (NN+127)/128), 256>>>(p_h2, 128, W1, 512, b1, p_ffn1, 512,
                                                 nullptr, 0, NN, 128);
    k_gemm128<2><<<dim3(1, (NN+127)/128), 256>>>(p_ffn1, 512, W2, 128, b2, out, 128,
                                                 p_xattn, 128, NN, 512);

    k_xn<<<(NN + 7)/8, 256>>>(out, eung, eunb);
    k_edge128<<<EE/128, 256, 128*132*4>>>(src, dst, ea, euW, eub, eueg, eueb,
                                          out + (size_t)NN*DIM);
}